// round 4
// baseline (speedup 1.0000x reference)
#include <cuda_runtime.h>

// Problem constants
#define B_ROWS 16
#define NCOL 2048
#define M 4096          // flat rows
#define D 8
#define NC 65536
#define ROWS_PER_M 256  // flat rows per batch row

// Argmin tunables
#define R_PER_THREAD 4
#define NWARPS 8
#define ROWS_PER_BLOCK (NWARPS * R_PER_THREAD)   // 32
#define NSEG 8
#define SEG_CODES (NC / NSEG)                    // 8192
#define TILE 512                                 // codes per shared tile
#define TILE2 (TILE / 2)                         // code-pairs per tile

typedef unsigned long long ull;

// Scratch
__device__ float g_scale[B_ROWS];
__device__ float g_cnorm[NC];
__device__ ull   g_key[M];          // (monotone dist bits << 32) | tileId
__device__ int   g_idx[M];
__device__ float g_sums[NC * D];
__device__ float g_counts[NC];

__device__ __forceinline__ ull pack2(float lo, float hi) {
    ull r;
    asm("mov.b64 %0, {%1, %2};" : "=l"(r) : "f"(lo), "f"(hi));
    return r;
}
__device__ __forceinline__ void unpack2(ull v, float& lo, float& hi) {
    asm("mov.b64 {%0, %1}, %2;" : "=f"(lo), "=f"(hi) : "l"(v));
}
__device__ __forceinline__ void fma2(ull& d, ull a, ull b) {
    asm("fma.rn.f32x2 %0, %1, %2, %3;" : "=l"(d) : "l"(a), "l"(b), "l"(d));
}

// ---------------------------------------------------------------------------
__global__ void k_scale(const float* __restrict__ x) {
    __shared__ float sh[256];
    int b = blockIdx.x;
    const float* row = x + b * NCOL;
    float s = 0.f;
    for (int i = threadIdx.x; i < NCOL; i += blockDim.x) s += fabsf(row[i]);
    sh[threadIdx.x] = s;
    __syncthreads();
    for (int off = 128; off > 0; off >>= 1) {
        if (threadIdx.x < off) sh[threadIdx.x] += sh[threadIdx.x + off];
        __syncthreads();
    }
    if (threadIdx.x == 0) g_scale[b] = sh[0] * (1.0f / NCOL);
}

// ---------------------------------------------------------------------------
__global__ void k_cnorm(const float* __restrict__ cb) {
    int c = blockIdx.x * blockDim.x + threadIdx.x;
    if (c < NC) {
        const float4* p = (const float4*)(cb + c * D);
        float4 a = p[0], b4 = p[1];
        g_cnorm[c] = a.x * a.x + a.y * a.y + a.z * a.z + a.w * a.w +
                     b4.x * b4.x + b4.y * b4.y + b4.z * b4.z + b4.w * b4.w;
    }
}

// ---------------------------------------------------------------------------
__global__ void k_init() {
    int t = blockIdx.x * blockDim.x + threadIdx.x;
    if (t < NC * D) g_sums[t] = 0.f;
    if (t < NC) g_counts[t] = 0.f;
    if (t < M) g_key[t] = 0xFFFFFFFFFFFFFFFFull;
}

// ---------------------------------------------------------------------------
// Pass 1: min distance per row, tracking only (minVal, winning tile).
// Inner loop = FFMA2 + FMNMX only (no predicated index selects).
// ---------------------------------------------------------------------------
__global__ void __launch_bounds__(256, 2) k_argmin(const float* __restrict__ x,
                                                   const float* __restrict__ cb) {
    __shared__ float4 sh4[4][TILE2];   // 16 KB
    __shared__ float2 shcn[TILE2];     // 2 KB

    int row0 = blockIdx.x * ROWS_PER_BLOCK;
    int segBase = blockIdx.y * SEG_CODES;
    int ct = threadIdx.x & 31;
    int w = threadIdx.x >> 5;
    int myrow0 = row0 + w * R_PER_THREAD;

    // Duplicated (-2*x/scale) query pairs
    ull f2[R_PER_THREAD][D];
#pragma unroll
    for (int r = 0; r < R_PER_THREAD; r++) {
        int m = myrow0 + r;
        float c0 = -2.0f / g_scale[m / ROWS_PER_M];
        const float4* xr = (const float4*)(x + m * D);
        float4 a = xr[0], b = xr[1];
        f2[r][0] = pack2(a.x * c0, a.x * c0);
        f2[r][1] = pack2(a.y * c0, a.y * c0);
        f2[r][2] = pack2(a.z * c0, a.z * c0);
        f2[r][3] = pack2(a.w * c0, a.w * c0);
        f2[r][4] = pack2(b.x * c0, b.x * c0);
        f2[r][5] = pack2(b.y * c0, b.y * c0);
        f2[r][6] = pack2(b.z * c0, b.z * c0);
        f2[r][7] = pack2(b.w * c0, b.w * c0);
    }

    float bestV[R_PER_THREAD];
    int bestT[R_PER_THREAD];
#pragma unroll
    for (int r = 0; r < R_PER_THREAD; r++) { bestV[r] = 3.4e38f; bestT[r] = 0; }

    const float4* cbv = (const float4*)cb;   // 2 float4s per code

    for (int t0 = 0; t0 < SEG_CODES; t0 += TILE) {
        __syncthreads();
        // Stage: TILE2 pairs x 2 halves = 512 tasks, 2 per thread
#pragma unroll
        for (int q = threadIdx.x; q < TILE2 * 2; q += 256) {
            int c2 = q >> 1;
            int h = q & 1;                    // dims 4h..4h+3
            int code0 = segBase + t0 + 2 * c2;
            float4 a = cbv[code0 * 2 + h];
            float4 b = cbv[code0 * 2 + 2 + h];
            sh4[2 * h + 0][c2] = make_float4(a.x, b.x, a.y, b.y);
            sh4[2 * h + 1][c2] = make_float4(a.z, b.z, a.w, b.w);
        }
        shcn[threadIdx.x] = ((const float2*)g_cnorm)[(segBase + t0) / 2 + threadIdx.x];
        __syncthreads();

        // Per-tile lane-local mins (value only)
        float pl[R_PER_THREAD], ph[R_PER_THREAD];
#pragma unroll
        for (int r = 0; r < R_PER_THREAD; r++) { pl[r] = 3.4e38f; ph[r] = 3.4e38f; }

#pragma unroll 4
        for (int i = 0; i < TILE2 / 32; i++) {
            int c2 = ct + 32 * i;
            ulonglong2 q0 = *(const ulonglong2*)&sh4[0][c2];
            ulonglong2 q1 = *(const ulonglong2*)&sh4[1][c2];
            ulonglong2 q2 = *(const ulonglong2*)&sh4[2][c2];
            ulonglong2 q3 = *(const ulonglong2*)&sh4[3][c2];
            ull cn2 = *(const ull*)&shcn[c2];
#pragma unroll
            for (int r = 0; r < R_PER_THREAD; r++) {
                ull d = cn2;
                fma2(d, f2[r][0], q0.x);
                fma2(d, f2[r][1], q0.y);
                fma2(d, f2[r][2], q1.x);
                fma2(d, f2[r][3], q1.y);
                fma2(d, f2[r][4], q2.x);
                fma2(d, f2[r][5], q2.y);
                fma2(d, f2[r][6], q3.x);
                fma2(d, f2[r][7], q3.y);
                float de, dodd;
                unpack2(d, de, dodd);
                pl[r] = fminf(pl[r], de);
                ph[r] = fminf(ph[r], dodd);
            }
        }

        int tileId = (segBase + t0) >> 9;   // global tile index (idx order)
#pragma unroll
        for (int r = 0; r < R_PER_THREAD; r++) {
            float tmin = fminf(pl[r], ph[r]);
            if (tmin < bestV[r]) { bestV[r] = tmin; bestT[r] = tileId; }
        }
    }

    // Warp reduce lexicographic (val, tile) across 32 code lanes
#pragma unroll
    for (int r = 0; r < R_PER_THREAD; r++) {
        float d = bestV[r];
        int t = bestT[r];
        for (int off = 16; off > 0; off >>= 1) {
            float d2 = __shfl_down_sync(0xffffffffu, d, off);
            int t2 = __shfl_down_sync(0xffffffffu, t, off);
            if (d2 < d || (d2 == d && t2 < t)) { d = d2; t = t2; }
        }
        if (ct == 0) {
            unsigned int ud = __float_as_uint(d);
            ud = (ud & 0x80000000u) ? ~ud : (ud | 0x80000000u);
            ull key = ((ull)ud << 32) | (unsigned int)t;
            atomicMin(&g_key[myrow0 + r], key);
        }
    }
}

// ---------------------------------------------------------------------------
// Pass 2: one warp per row rescans the winning 512-code tile with the exact
// same fma2 chain (bit-identical distances) and takes the first index whose
// distance equals the recorded min.
// ---------------------------------------------------------------------------
__global__ void __launch_bounds__(256) k_resolve(const float* __restrict__ x,
                                                 const float* __restrict__ cb) {
    int m = blockIdx.x * (blockDim.x >> 5) + (threadIdx.x >> 5);
    int lane = threadIdx.x & 31;
    if (m >= M) return;

    ull key = g_key[m];
    int tile = (int)(key & 0xFFFFFFFFu);
    unsigned int ud = (unsigned int)(key >> 32);
    ud = (ud & 0x80000000u) ? (ud & 0x7FFFFFFFu) : ~ud;  // inverse monotone map
    float target = __uint_as_float(ud);

    float c0 = -2.0f / g_scale[m / ROWS_PER_M];
    const float4* xr = (const float4*)(x + m * D);
    float4 a = xr[0], b = xr[1];
    ull f2r[D];
    f2r[0] = pack2(a.x * c0, a.x * c0);
    f2r[1] = pack2(a.y * c0, a.y * c0);
    f2r[2] = pack2(a.z * c0, a.z * c0);
    f2r[3] = pack2(a.w * c0, a.w * c0);
    f2r[4] = pack2(b.x * c0, b.x * c0);
    f2r[5] = pack2(b.y * c0, b.y * c0);
    f2r[6] = pack2(b.z * c0, b.z * c0);
    f2r[7] = pack2(b.w * c0, b.w * c0);

    const float4* cbv = (const float4*)cb;
    int base = tile * TILE;
    int best = 0x7FFFFFFF;

#pragma unroll
    for (int p = 0; p < TILE2 / 32; p++) {
        int c2 = lane + 32 * p;
        int code0 = base + 2 * c2;
        float4 a0 = cbv[code0 * 2 + 0];
        float4 a1 = cbv[code0 * 2 + 1];
        float4 b0 = cbv[code0 * 2 + 2];
        float4 b1 = cbv[code0 * 2 + 3];
        ull d = pack2(g_cnorm[code0], g_cnorm[code0 + 1]);
        fma2(d, f2r[0], pack2(a0.x, b0.x));
        fma2(d, f2r[1], pack2(a0.y, b0.y));
        fma2(d, f2r[2], pack2(a0.z, b0.z));
        fma2(d, f2r[3], pack2(a0.w, b0.w));
        fma2(d, f2r[4], pack2(a1.x, b1.x));
        fma2(d, f2r[5], pack2(a1.y, b1.y));
        fma2(d, f2r[6], pack2(a1.z, b1.z));
        fma2(d, f2r[7], pack2(a1.w, b1.w));
        float de, dodd;
        unpack2(d, de, dodd);
        if (de == target) best = min(best, code0);
        else if (dodd == target) best = min(best, code0 + 1);
    }

    for (int off = 16; off > 0; off >>= 1)
        best = min(best, __shfl_down_sync(0xffffffffu, best, off));
    if (lane == 0) g_idx[m] = best;
}

// ---------------------------------------------------------------------------
__global__ void k_scatter(const float* __restrict__ x) {
    int m = blockIdx.x * blockDim.x + threadIdx.x;
    if (m >= M) return;
    int idx = g_idx[m];
    float inv = 1.0f / g_scale[m / ROWS_PER_M];
    atomicAdd(&g_counts[idx], 1.f);
    const float* xr = x + m * D;
#pragma unroll
    for (int j = 0; j < D; j++) atomicAdd(&g_sums[idx * D + j], xr[j] * inv);
}

// ---------------------------------------------------------------------------
__global__ void k_gather(float* __restrict__ out) {
    int t = blockIdx.x * blockDim.x + threadIdx.x;
    if (t >= M * D) return;
    int m = t >> 3;
    int j = t & 7;
    int idx = g_idx[m];
    float cnt = g_counts[idx];
    cnt = cnt < 1.f ? 1.f : cnt;
    out[t] = g_scale[m / ROWS_PER_M] * (g_sums[idx * D + j] / cnt);
}

// ---------------------------------------------------------------------------
extern "C" void kernel_launch(void* const* d_in, const int* in_sizes, int n_in,
                              void* d_out, int out_size) {
    const float* x = (const float*)d_in[0];
    const float* cb = (const float*)d_in[1];
    if (n_in >= 2 && in_sizes[0] > in_sizes[1]) {
        x = (const float*)d_in[1];
        cb = (const float*)d_in[0];
    }
    float* out = (float*)d_out;

    k_scale<<<B_ROWS, 256>>>(x);
    k_cnorm<<<NC / 256, 256>>>(cb);
    k_init<<<(NC * D + 255) / 256, 256>>>();
    dim3 grid(M / ROWS_PER_BLOCK, NSEG);
    k_argmin<<<grid, 256>>>(x, cb);
    k_resolve<<<M / 8, 256>>>(x, cb);
    k_scatter<<<(M + 255) / 256, 256>>>(x);
    k_gather<<<(M * D + 255) / 256, 256>>>(out);
}

// round 5
// speedup vs baseline: 1.2570x; 1.2570x over previous
#include <cuda_runtime.h>

// Problem constants
#define B_ROWS 16
#define NCOL 2048
#define M 4096          // flat rows
#define D 8
#define NC 65536
#define ROWS_PER_M 256  // flat rows per batch row

// Argmin tunables
#define R_PER_THREAD 4
#define NWARPS 8
#define ROWS_PER_BLOCK (NWARPS * R_PER_THREAD)   // 32
#define NSEG 8
#define SEG_CODES (NC / NSEG)                    // 8192
#define TILE 512                                 // codes per shared tile
#define TILE2 (TILE / 2)                         // 256 code-pairs = blockDim
#define NTILES (SEG_CODES / TILE)                // 16

typedef unsigned long long ull;

// Scratch
__device__ float g_scale[B_ROWS];
__device__ float g_cnorm[NC];
__device__ float4 g_cbi[4][NC / 2];  // interleaved code-pair planes (dim-pairs)
__device__ float2 g_cni[NC / 2];     // norms per pair
__device__ ull   g_key[M];           // (monotone dist bits << 32) | tileId
__device__ int   g_idx[M];
__device__ float g_sums[NC * D];
__device__ float g_counts[NC];

__device__ __forceinline__ ull pack2(float lo, float hi) {
    ull r;
    asm("mov.b64 %0, {%1, %2};" : "=l"(r) : "f"(lo), "f"(hi));
    return r;
}
__device__ __forceinline__ void unpack2(ull v, float& lo, float& hi) {
    asm("mov.b64 {%0, %1}, %2;" : "=f"(lo), "=f"(hi) : "l"(v));
}
__device__ __forceinline__ void fma2(ull& d, ull a, ull b) {
    asm("fma.rn.f32x2 %0, %1, %2, %3;" : "=l"(d) : "l"(a), "l"(b), "l"(d));
}
__device__ __forceinline__ unsigned smem_u32(const void* p) {
    return (unsigned)__cvta_generic_to_shared(p);
}
__device__ __forceinline__ void cpa16(unsigned dst, const void* src) {
    asm volatile("cp.async.cg.shared.global [%0], [%1], 16;" :: "r"(dst), "l"(src));
}
__device__ __forceinline__ void cpa8(unsigned dst, const void* src) {
    asm volatile("cp.async.ca.shared.global [%0], [%1], 8;" :: "r"(dst), "l"(src));
}
__device__ __forceinline__ void cpa_commit() {
    asm volatile("cp.async.commit_group;");
}
template <int N>
__device__ __forceinline__ void cpa_wait() {
    asm volatile("cp.async.wait_group %0;" :: "n"(N));
}

// ---------------------------------------------------------------------------
__global__ void k_scale(const float* __restrict__ x) {
    __shared__ float sh[256];
    int b = blockIdx.x;
    const float* row = x + b * NCOL;
    float s = 0.f;
    for (int i = threadIdx.x; i < NCOL; i += blockDim.x) s += fabsf(row[i]);
    sh[threadIdx.x] = s;
    __syncthreads();
    for (int off = 128; off > 0; off >>= 1) {
        if (threadIdx.x < off) sh[threadIdx.x] += sh[threadIdx.x + off];
        __syncthreads();
    }
    if (threadIdx.x == 0) g_scale[b] = sh[0] * (1.0f / NCOL);
}

// ---------------------------------------------------------------------------
// Pre-interleave codebook into 4 dim-pair planes + pair norms (also g_cnorm).
// Plane layout matches the argmin shared tile exactly -> staging = raw copy.
// ---------------------------------------------------------------------------
__global__ void k_prep(const float* __restrict__ cb) {
    int p = blockIdx.x * blockDim.x + threadIdx.x;  // pair id
    if (p >= NC / 2) return;
    const float4* cbv = (const float4*)cb;
    float4 a0 = cbv[4 * p + 0], a1 = cbv[4 * p + 1];  // code 2p
    float4 b0 = cbv[4 * p + 2], b1 = cbv[4 * p + 3];  // code 2p+1
    g_cbi[0][p] = make_float4(a0.x, b0.x, a0.y, b0.y);
    g_cbi[1][p] = make_float4(a0.z, b0.z, a0.w, b0.w);
    g_cbi[2][p] = make_float4(a1.x, b1.x, a1.y, b1.y);
    g_cbi[3][p] = make_float4(a1.z, b1.z, a1.w, b1.w);
    float na = a0.x * a0.x + a0.y * a0.y + a0.z * a0.z + a0.w * a0.w +
               a1.x * a1.x + a1.y * a1.y + a1.z * a1.z + a1.w * a1.w;
    float nb = b0.x * b0.x + b0.y * b0.y + b0.z * b0.z + b0.w * b0.w +
               b1.x * b1.x + b1.y * b1.y + b1.z * b1.z + b1.w * b1.w;
    g_cni[p] = make_float2(na, nb);
    g_cnorm[2 * p] = na;
    g_cnorm[2 * p + 1] = nb;
}

// ---------------------------------------------------------------------------
__global__ void k_init() {
    int t = blockIdx.x * blockDim.x + threadIdx.x;
    if (t < NC * D) g_sums[t] = 0.f;
    if (t < NC) g_counts[t] = 0.f;
    if (t < M) g_key[t] = 0xFFFFFFFFFFFFFFFFull;
}

// ---------------------------------------------------------------------------
// Pass 1: per-row min distance + winning tile. Double-buffered cp.async
// staging (tile t+1 loads overlap tile t compute). Inner loop: FFMA2 + FMNMX.
// ---------------------------------------------------------------------------
__global__ void __launch_bounds__(256, 2) k_argmin(const float* __restrict__ x) {
    __shared__ float4 sh4[2][4][TILE2];   // 32 KB (double-buffered planes)
    __shared__ float2 shcn[2][TILE2];     // 4 KB

    int row0 = blockIdx.x * ROWS_PER_BLOCK;
    int segBase = blockIdx.y * SEG_CODES;
    int ct = threadIdx.x & 31;
    int w = threadIdx.x >> 5;
    int myrow0 = row0 + w * R_PER_THREAD;
    int tid = threadIdx.x;

    // Duplicated (-2*x/scale) query pairs
    ull f2[R_PER_THREAD][D];
#pragma unroll
    for (int r = 0; r < R_PER_THREAD; r++) {
        int m = myrow0 + r;
        float c0 = -2.0f / g_scale[m / ROWS_PER_M];
        const float4* xr = (const float4*)(x + m * D);
        float4 a = xr[0], b = xr[1];
        f2[r][0] = pack2(a.x * c0, a.x * c0);
        f2[r][1] = pack2(a.y * c0, a.y * c0);
        f2[r][2] = pack2(a.z * c0, a.z * c0);
        f2[r][3] = pack2(a.w * c0, a.w * c0);
        f2[r][4] = pack2(b.x * c0, b.x * c0);
        f2[r][5] = pack2(b.y * c0, b.y * c0);
        f2[r][6] = pack2(b.z * c0, b.z * c0);
        f2[r][7] = pack2(b.w * c0, b.w * c0);
    }

    float bestV[R_PER_THREAD];
    int bestT[R_PER_THREAD];
#pragma unroll
    for (int r = 0; r < R_PER_THREAD; r++) { bestV[r] = 3.4e38f; bestT[r] = 0; }

    int pairBase0 = segBase >> 1;
    // Prologue: stage tile 0 into buffer 0
    {
#pragma unroll
        for (int rec = 0; rec < 4; rec++)
            cpa16(smem_u32(&sh4[0][rec][tid]), &g_cbi[rec][pairBase0 + tid]);
        cpa8(smem_u32(&shcn[0][tid]), &g_cni[pairBase0 + tid]);
        cpa_commit();
    }

    for (int t = 0; t < NTILES; t++) {
        int b = t & 1;
        if (t > 0) __syncthreads();  // protect buffer b^1 from overwrite
        if (t + 1 < NTILES) {
            int pb = pairBase0 + (t + 1) * TILE2;
#pragma unroll
            for (int rec = 0; rec < 4; rec++)
                cpa16(smem_u32(&sh4[b ^ 1][rec][tid]), &g_cbi[rec][pb + tid]);
            cpa8(smem_u32(&shcn[b ^ 1][tid]), &g_cni[pb + tid]);
            cpa_commit();
            cpa_wait<1>();   // group t complete (in flight for a full tile)
        } else {
            cpa_wait<0>();
        }
        __syncthreads();

        float pl[R_PER_THREAD], ph[R_PER_THREAD];
#pragma unroll
        for (int r = 0; r < R_PER_THREAD; r++) { pl[r] = 3.4e38f; ph[r] = 3.4e38f; }

#pragma unroll 4
        for (int i = 0; i < TILE2 / 32; i++) {
            int c2 = ct + 32 * i;
            ulonglong2 q0 = *(const ulonglong2*)&sh4[b][0][c2];
            ulonglong2 q1 = *(const ulonglong2*)&sh4[b][1][c2];
            ulonglong2 q2 = *(const ulonglong2*)&sh4[b][2][c2];
            ulonglong2 q3 = *(const ulonglong2*)&sh4[b][3][c2];
            ull cn2 = *(const ull*)&shcn[b][c2];
#pragma unroll
            for (int r = 0; r < R_PER_THREAD; r++) {
                ull d = cn2;
                fma2(d, f2[r][0], q0.x);
                fma2(d, f2[r][1], q0.y);
                fma2(d, f2[r][2], q1.x);
                fma2(d, f2[r][3], q1.y);
                fma2(d, f2[r][4], q2.x);
                fma2(d, f2[r][5], q2.y);
                fma2(d, f2[r][6], q3.x);
                fma2(d, f2[r][7], q3.y);
                float de, dodd;
                unpack2(d, de, dodd);
                pl[r] = fminf(pl[r], de);
                ph[r] = fminf(ph[r], dodd);
            }
        }

        int tileId = (segBase >> 9) + t;   // global 512-code tile index
#pragma unroll
        for (int r = 0; r < R_PER_THREAD; r++) {
            float tmin = fminf(pl[r], ph[r]);
            if (tmin < bestV[r]) { bestV[r] = tmin; bestT[r] = tileId; }
        }
    }

    // Warp reduce lexicographic (val, tile) across 32 code lanes
#pragma unroll
    for (int r = 0; r < R_PER_THREAD; r++) {
        float d = bestV[r];
        int t = bestT[r];
        for (int off = 16; off > 0; off >>= 1) {
            float d2 = __shfl_down_sync(0xffffffffu, d, off);
            int t2 = __shfl_down_sync(0xffffffffu, t, off);
            if (d2 < d || (d2 == d && t2 < t)) { d = d2; t = t2; }
        }
        if (ct == 0) {
            unsigned int ud = __float_as_uint(d);
            ud = (ud & 0x80000000u) ? ~ud : (ud | 0x80000000u);
            ull key = ((ull)ud << 32) | (unsigned int)t;
            atomicMin(&g_key[myrow0 + r], key);
        }
    }
}

// ---------------------------------------------------------------------------
// Pass 2: one warp per row rescans its winning 512-code tile with the exact
// fma2 chain (bit-identical distances); first index matching the min wins.
// ---------------------------------------------------------------------------
__global__ void __launch_bounds__(256) k_resolve(const float* __restrict__ x,
                                                 const float* __restrict__ cb) {
    int m = blockIdx.x * (blockDim.x >> 5) + (threadIdx.x >> 5);
    int lane = threadIdx.x & 31;
    if (m >= M) return;

    ull key = g_key[m];
    int tile = (int)(key & 0xFFFFFFFFu);
    unsigned int ud = (unsigned int)(key >> 32);
    ud = (ud & 0x80000000u) ? (ud & 0x7FFFFFFFu) : ~ud;  // inverse monotone map
    float target = __uint_as_float(ud);

    float c0 = -2.0f / g_scale[m / ROWS_PER_M];
    const float4* xr = (const float4*)(x + m * D);
    float4 a = xr[0], b = xr[1];
    ull f2r[D];
    f2r[0] = pack2(a.x * c0, a.x * c0);
    f2r[1] = pack2(a.y * c0, a.y * c0);
    f2r[2] = pack2(a.z * c0, a.z * c0);
    f2r[3] = pack2(a.w * c0, a.w * c0);
    f2r[4] = pack2(b.x * c0, b.x * c0);
    f2r[5] = pack2(b.y * c0, b.y * c0);
    f2r[6] = pack2(b.z * c0, b.z * c0);
    f2r[7] = pack2(b.w * c0, b.w * c0);

    const float4* cbv = (const float4*)cb;
    int base = tile * TILE;
    int best = 0x7FFFFFFF;

#pragma unroll
    for (int p = 0; p < TILE2 / 32; p++) {
        int c2 = lane + 32 * p;
        int code0 = base + 2 * c2;
        float4 a0 = cbv[code0 * 2 + 0];
        float4 a1 = cbv[code0 * 2 + 1];
        float4 b0 = cbv[code0 * 2 + 2];
        float4 b1 = cbv[code0 * 2 + 3];
        ull d = pack2(g_cnorm[code0], g_cnorm[code0 + 1]);
        fma2(d, f2r[0], pack2(a0.x, b0.x));
        fma2(d, f2r[1], pack2(a0.y, b0.y));
        fma2(d, f2r[2], pack2(a0.z, b0.z));
        fma2(d, f2r[3], pack2(a0.w, b0.w));
        fma2(d, f2r[4], pack2(a1.x, b1.x));
        fma2(d, f2r[5], pack2(a1.y, b1.y));
        fma2(d, f2r[6], pack2(a1.z, b1.z));
        fma2(d, f2r[7], pack2(a1.w, b1.w));
        float de, dodd;
        unpack2(d, de, dodd);
        if (de == target) best = min(best, code0);
        else if (dodd == target) best = min(best, code0 + 1);
    }

    for (int off = 16; off > 0; off >>= 1)
        best = min(best, __shfl_down_sync(0xffffffffu, best, off));
    if (lane == 0) g_idx[m] = best;
}

// ---------------------------------------------------------------------------
__global__ void k_scatter(const float* __restrict__ x) {
    int m = blockIdx.x * blockDim.x + threadIdx.x;
    if (m >= M) return;
    int idx = g_idx[m];
    float inv = 1.0f / g_scale[m / ROWS_PER_M];
    atomicAdd(&g_counts[idx], 1.f);
    const float* xr = x + m * D;
#pragma unroll
    for (int j = 0; j < D; j++) atomicAdd(&g_sums[idx * D + j], xr[j] * inv);
}

// ---------------------------------------------------------------------------
__global__ void k_gather(float* __restrict__ out) {
    int t = blockIdx.x * blockDim.x + threadIdx.x;
    if (t >= M * D) return;
    int m = t >> 3;
    int j = t & 7;
    int idx = g_idx[m];
    float cnt = g_counts[idx];
    cnt = cnt < 1.f ? 1.f : cnt;
    out[t] = g_scale[m / ROWS_PER_M] * (g_sums[idx * D + j] / cnt);
}

// ---------------------------------------------------------------------------
extern "C" void kernel_launch(void* const* d_in, const int* in_sizes, int n_in,
                              void* d_out, int out_size) {
    const float* x = (const float*)d_in[0];
    const float* cb = (const float*)d_in[1];
    if (n_in >= 2 && in_sizes[0] > in_sizes[1]) {
        x = (const float*)d_in[1];
        cb = (const float*)d_in[0];
    }
    float* out = (float*)d_out;

    k_scale<<<B_ROWS, 256>>>(x);
    k_prep<<<(NC / 2) / 256, 256>>>(cb);
    k_init<<<(NC * D + 255) / 256, 256>>>();
    dim3 grid(M / ROWS_PER_BLOCK, NSEG);
    k_argmin<<<grid, 256>>>(x);
    k_resolve<<<M / 8, 256>>>(x, cb);
    k_scatter<<<(M + 255) / 256, 256>>>(x);
    k_gather<<<(M * D + 255) / 256, 256>>>(out);
}